// round 15
// baseline (speedup 1.0000x reference)
#include <cuda_runtime.h>
#include <cuda_bf16.h>
#include <cuda_fp16.h>
#include <cstdint>

#define NN 100000
#define NE 1600000
#define NF 128
#define NC 40
#define NB_SCAN ((NN + 1023) / 1024)
#define PADH 136   // halves per smem row (128-wide tiles): 272 B stride
#define PAD40 72   // halves per smem row (64-wide B tile): 144 B stride

// Scratch (device globals)
__device__ __align__(16) float g_dinv[NN];
__device__ __align__(16) __half g_th[(size_t)NN * NF];   // Y messages (fp16)
__device__ __align__(16) __half g_ah[(size_t)NN * NF];   // activations (fp16)
__device__ __align__(16) __half g_wh[3 * 128 * 128];     // fp16 weights (layers 1-3)
__device__ __align__(16) __half g_w4h[128 * 64];         // fp16 W4 padded to 64 cols
__device__ int g_cnt[NN];
__device__ int g_rs[NN + 1];
__device__ int g_cursor[NN];
__device__ int g_csr[NE];
__device__ int g_bsum[NB_SCAN];
__device__ int g_boff[NB_SCAN];

// ---------------------------------------------------------------------------
// Helpers
// ---------------------------------------------------------------------------
__device__ __forceinline__ void acc8(float* f, uint4 v) {
    float2 a = __half22float2(*(__half2*)&v.x);
    float2 b = __half22float2(*(__half2*)&v.y);
    float2 c = __half22float2(*(__half2*)&v.z);
    float2 d = __half22float2(*(__half2*)&v.w);
    f[0] += a.x; f[1] += a.y; f[2] += b.x; f[3] += b.y;
    f[4] += c.x; f[5] += c.y; f[6] += d.x; f[7] += d.y;
}

__device__ __forceinline__ uint4 relu_h8(uint4 v) {
    __half2 z = __float2half2_rn(0.f);
    __half2* h = (__half2*)&v;
    h[0] = __hmax2(h[0], z); h[1] = __hmax2(h[1], z);
    h[2] = __hmax2(h[2], z); h[3] = __hmax2(h[3], z);
    return v;
}

// ---------------------------------------------------------------------------
// CSR build
// ---------------------------------------------------------------------------
__global__ void k_zero(int* cnt) {
    int i = blockIdx.x * blockDim.x + threadIdx.x;
    if (i < NN) cnt[i] = 0;
}

__global__ void k_count(const int* __restrict__ ei, int* cnt) {
    int e = blockIdx.x * blockDim.x + threadIdx.x;
    if (e < NE) atomicAdd(&cnt[ei[NE + e]], 1);
}

__global__ void k_scan1(const int* __restrict__ cnt, int* rs, int* bsum) {
    __shared__ int s[1024];
    int i = blockIdx.x * 1024 + threadIdx.x;
    int v = (i < NN) ? cnt[i] : 0;
    s[threadIdx.x] = v;
    __syncthreads();
#pragma unroll
    for (int o = 1; o < 1024; o <<= 1) {
        int t = (threadIdx.x >= o) ? s[threadIdx.x - o] : 0;
        __syncthreads();
        s[threadIdx.x] += t;
        __syncthreads();
    }
    if (i < NN) rs[i] = s[threadIdx.x] - v;
    if (threadIdx.x == 1023) bsum[blockIdx.x] = s[1023];
}

// parallel Hillis-Steele over NB_SCAN (<=128) elements
__global__ void k_scan2(const int* __restrict__ bsum, int* boff) {
    __shared__ int s[128];
    int v = (threadIdx.x < NB_SCAN) ? bsum[threadIdx.x] : 0;
    s[threadIdx.x] = v;
    __syncthreads();
#pragma unroll
    for (int o = 1; o < 128; o <<= 1) {
        int t = (threadIdx.x >= o) ? s[threadIdx.x - o] : 0;
        __syncthreads();
        s[threadIdx.x] += t;
        __syncthreads();
    }
    if (threadIdx.x < NB_SCAN) boff[threadIdx.x] = s[threadIdx.x] - v;  // exclusive
}

// scan3 + dinv fused (dinv from cnt; consumed first by gemm1 which runs later)
__global__ void k_scan3(int* rs, int* cursor, const int* __restrict__ boff,
                        const int* __restrict__ cnt, float* __restrict__ dinv) {
    int i = blockIdx.x * blockDim.x + threadIdx.x;
    if (i < NN) {
        int v = rs[i] + boff[i >> 10];
        rs[i] = v;
        cursor[i] = v;
        dinv[i] = rsqrtf((float)(cnt[i] + 1));
    }
    if (i == 0) rs[NN] = NE;
}

__global__ void k_fill(const int* __restrict__ ei, int* cursor, int* csr) {
    int e = blockIdx.x * blockDim.x + threadIdx.x;
    if (e >= NE) return;
    int src = ei[e];
    int dst = ei[NE + e];
    int pos = atomicAdd(&cursor[dst], 1);
    csr[pos] = src;
}

__global__ void k_convW(const float* __restrict__ W, __half* __restrict__ Wh, int n) {
    int i = blockIdx.x * blockDim.x + threadIdx.x;
    if (i < n) Wh[i] = __float2half(W[i]);
}

__global__ void k_convW4(const float* __restrict__ W, __half* __restrict__ Wh) {
    int i = blockIdx.x * blockDim.x + threadIdx.x;
    if (i < 128 * 64) {
        int k = i >> 6, c = i & 63;
        Wh[i] = (c < 40) ? __float2half(W[k * 40 + c]) : __float2half(0.f);
    }
}

// ---------------------------------------------------------------------------
// Tensor-core GEMM: Yh[M,128] = half( dinv * (relu?(X) @ W) )
// BM=128, 512 threads, 16 warps = 8(M) x 2(N), warp tile m16 x n64.
// ---------------------------------------------------------------------------
template <typename TIN, bool RELU>
__global__ void __launch_bounds__(512)
k_gemm128_mma(const TIN* __restrict__ X, const __half* __restrict__ Wh,
              const float* __restrict__ dinv, __half* __restrict__ Yh, int M) {
    extern __shared__ __half sh[];
    __half* As = sh;                  // 128 x PADH
    __half* Bs = sh + 128 * PADH;     // 128 x PADH

    const int t    = threadIdx.x;
    const int warp = t >> 5;
    const int lane = t & 31;
    const int m0   = blockIdx.x * 128;
    const int wm   = (warp >> 1) * 16;
    const int wn   = (warp & 1) * 64;

    if constexpr (sizeof(TIN) == 4) {
#pragma unroll
        for (int i = 0; i < 8; i++) {
            int idx = t + i * 512;
            int row = idx >> 5;
            int c4  = (idx & 31) * 4;
            float4 v = make_float4(0.f, 0.f, 0.f, 0.f);
            if (m0 + row < M)
                v = *(const float4*)&X[(size_t)(m0 + row) * 128 + c4];
            if (RELU) {
                v.x = fmaxf(v.x, 0.f); v.y = fmaxf(v.y, 0.f);
                v.z = fmaxf(v.z, 0.f); v.w = fmaxf(v.w, 0.f);
            }
            __half2 h0 = __float22half2_rn(make_float2(v.x, v.y));
            __half2 h1 = __float22half2_rn(make_float2(v.z, v.w));
            uint2 pkt;
            pkt.x = *(unsigned*)&h0;
            pkt.y = *(unsigned*)&h1;
            *(uint2*)&As[row * PADH + c4] = pkt;
        }
    } else {
#pragma unroll
        for (int i = 0; i < 4; i++) {
            int idx = t + i * 512;
            int row = idx >> 4;
            int c8  = (idx & 15) * 8;
            uint4 v = make_uint4(0, 0, 0, 0);
            if (m0 + row < M)
                v = *(const uint4*)&X[(size_t)(m0 + row) * 128 + c8];
            if (RELU) v = relu_h8(v);
            *(uint4*)&As[row * PADH + c8] = v;
        }
    }
#pragma unroll
    for (int i = 0; i < 4; i++) {
        int idx = t + i * 512;
        int row = idx >> 4;
        int c8  = (idx & 15) * 8;
        *(uint4*)&Bs[row * PADH + c8] = *(const uint4*)&Wh[row * 128 + c8];
    }
    __syncthreads();

    float acc[8][4] = {};

    unsigned a_base = (unsigned)__cvta_generic_to_shared(As);
    unsigned b_base = (unsigned)__cvta_generic_to_shared(Bs);
    int lrow = lane & 15;
    int lcol = (lane >> 4) * 8;

#pragma unroll
    for (int k0 = 0; k0 < 128; k0 += 16) {
        unsigned a_addr = a_base + ((wm + lrow) * PADH + k0 + lcol) * 2;
        unsigned r0, r1, r2, r3;
        asm volatile("ldmatrix.sync.aligned.m8n8.x4.shared.b16 {%0,%1,%2,%3}, [%4];"
                     : "=r"(r0), "=r"(r1), "=r"(r2), "=r"(r3) : "r"(a_addr));
#pragma unroll
        for (int j = 0; j < 4; j++) {
            unsigned b_addr = b_base + ((k0 + lrow) * PADH + wn + j * 16 + lcol) * 2;
            unsigned b0, b1, b2, b3;
            asm volatile("ldmatrix.sync.aligned.m8n8.x4.trans.shared.b16 {%0,%1,%2,%3}, [%4];"
                         : "=r"(b0), "=r"(b1), "=r"(b2), "=r"(b3) : "r"(b_addr));
            asm volatile("mma.sync.aligned.m16n8k16.row.col.f32.f16.f16.f32 "
                         "{%0,%1,%2,%3}, {%4,%5,%6,%7}, {%8,%9}, {%0,%1,%2,%3};"
                         : "+f"(acc[2*j][0]), "+f"(acc[2*j][1]),
                           "+f"(acc[2*j][2]), "+f"(acc[2*j][3])
                         : "r"(r0), "r"(r1), "r"(r2), "r"(r3), "r"(b0), "r"(b1));
            asm volatile("mma.sync.aligned.m16n8k16.row.col.f32.f16.f16.f32 "
                         "{%0,%1,%2,%3}, {%4,%5,%6,%7}, {%8,%9}, {%0,%1,%2,%3};"
                         : "+f"(acc[2*j+1][0]), "+f"(acc[2*j+1][1]),
                           "+f"(acc[2*j+1][2]), "+f"(acc[2*j+1][3])
                         : "r"(r0), "r"(r1), "r"(r2), "r"(r3), "r"(b2), "r"(b3));
        }
    }

    int rq = lane >> 2;
    int cq = 2 * (lane & 3);
    int row0 = m0 + wm + rq;
    int row1 = row0 + 8;
    float d0 = (row0 < M) ? __ldg(&dinv[row0]) : 0.f;
    float d1 = (row1 < M) ? __ldg(&dinv[row1]) : 0.f;
#pragma unroll
    for (int j = 0; j < 8; j++) {
        int col = wn + j * 8 + cq;
        if (row0 < M) {
            __half2 h = __float22half2_rn(make_float2(d0 * acc[j][0], d0 * acc[j][1]));
            *(unsigned*)&Yh[(size_t)row0 * 128 + col] = *(unsigned*)&h;
        }
        if (row1 < M) {
            __half2 h = __float22half2_rn(make_float2(d1 * acc[j][2], d1 * acc[j][3]));
            *(unsigned*)&Yh[(size_t)row1 * 128 + col] = *(unsigned*)&h;
        }
    }
}

// ---------------------------------------------------------------------------
// Tensor-core GEMM (layer 4): Yh[M,40] = half( dinv * (relu(Ah) @ W4pad) )
// ---------------------------------------------------------------------------
__global__ void __launch_bounds__(256)
k_gemm40_mma(const __half* __restrict__ Ah, const __half* __restrict__ W4h,
             const float* __restrict__ dinv, __half* __restrict__ Yh, int M) {
    extern __shared__ __half sh[];
    __half* As = sh;                  // 64 x PADH
    __half* Bs = sh + 64 * PADH;      // 128 x PAD40

    const int t    = threadIdx.x;
    const int warp = t >> 5;
    const int lane = t & 31;
    const int m0   = blockIdx.x * 64;
    const int wm   = (warp >> 1) * 16;
    const int wn   = (warp & 1) * 32;

#pragma unroll
    for (int i = 0; i < 4; i++) {
        int idx = t + i * 256;
        int row = idx >> 4;
        int c8  = (idx & 15) * 8;
        uint4 v = make_uint4(0, 0, 0, 0);
        if (m0 + row < M)
            v = *(const uint4*)&Ah[(size_t)(m0 + row) * 128 + c8];
        v = relu_h8(v);
        *(uint4*)&As[row * PADH + c8] = v;
    }
#pragma unroll
    for (int i = 0; i < 4; i++) {
        int idx = t + i * 256;
        int row = idx >> 3;
        int c8  = (idx & 7) * 8;
        *(uint4*)&Bs[row * PAD40 + c8] = *(const uint4*)&W4h[row * 64 + c8];
    }
    __syncthreads();

    float acc[4][4] = {};

    unsigned a_base = (unsigned)__cvta_generic_to_shared(As);
    unsigned b_base = (unsigned)__cvta_generic_to_shared(Bs);
    int lrow = lane & 15;
    int lcol = (lane >> 4) * 8;

#pragma unroll
    for (int k0 = 0; k0 < 128; k0 += 16) {
        unsigned a_addr = a_base + ((wm + lrow) * PADH + k0 + lcol) * 2;
        unsigned r0, r1, r2, r3;
        asm volatile("ldmatrix.sync.aligned.m8n8.x4.shared.b16 {%0,%1,%2,%3}, [%4];"
                     : "=r"(r0), "=r"(r1), "=r"(r2), "=r"(r3) : "r"(a_addr));
#pragma unroll
        for (int j = 0; j < 2; j++) {
            unsigned b_addr = b_base + ((k0 + lrow) * PAD40 + wn + j * 16 + lcol) * 2;
            unsigned b0, b1, b2, b3;
            asm volatile("ldmatrix.sync.aligned.m8n8.x4.trans.shared.b16 {%0,%1,%2,%3}, [%4];"
                         : "=r"(b0), "=r"(b1), "=r"(b2), "=r"(b3) : "r"(b_addr));
            asm volatile("mma.sync.aligned.m16n8k16.row.col.f32.f16.f16.f32 "
                         "{%0,%1,%2,%3}, {%4,%5,%6,%7}, {%8,%9}, {%0,%1,%2,%3};"
                         : "+f"(acc[2*j][0]), "+f"(acc[2*j][1]),
                           "+f"(acc[2*j][2]), "+f"(acc[2*j][3])
                         : "r"(r0), "r"(r1), "r"(r2), "r"(r3), "r"(b0), "r"(b1));
            asm volatile("mma.sync.aligned.m16n8k16.row.col.f32.f16.f16.f32 "
                         "{%0,%1,%2,%3}, {%4,%5,%6,%7}, {%8,%9}, {%0,%1,%2,%3};"
                         : "+f"(acc[2*j+1][0]), "+f"(acc[2*j+1][1]),
                           "+f"(acc[2*j+1][2]), "+f"(acc[2*j+1][3])
                         : "r"(r0), "r"(r1), "r"(r2), "r"(r3), "r"(b2), "r"(b3));
        }
    }

    int rq = lane >> 2;
    int cq = 2 * (lane & 3);
    int row0 = m0 + wm + rq;
    int row1 = row0 + 8;
    float d0 = (row0 < M) ? __ldg(&dinv[row0]) : 0.f;
    float d1 = (row1 < M) ? __ldg(&dinv[row1]) : 0.f;
#pragma unroll
    for (int j = 0; j < 4; j++) {
        int col = wn + j * 8 + cq;
        if (col < 40) {
            if (row0 < M) {
                __half2 h = __float22half2_rn(make_float2(d0 * acc[j][0], d0 * acc[j][1]));
                *(unsigned*)&Yh[(size_t)row0 * 40 + col] = *(unsigned*)&h;
            }
            if (row1 < M) {
                __half2 h = __float22half2_rn(make_float2(d1 * acc[j][2], d1 * acc[j][3]));
                *(unsigned*)&Yh[(size_t)row1 * 40 + col] = *(unsigned*)&h;
            }
        }
    }
}

// ---------------------------------------------------------------------------
// Aggregation gather (F=128): 16-lane group per node, uint4 loads,
// 8/4/1 unroll cascade for deep MLP.
// ---------------------------------------------------------------------------
template <bool WRITE_LATENT>
__global__ void k_agg128(const int* __restrict__ rs, const int* __restrict__ csr,
                         const __half* __restrict__ Yh, const float* __restrict__ dinv,
                         const float* __restrict__ bias, __half* __restrict__ Ah,
                         float* __restrict__ latent) {
    int node = blockIdx.x * (blockDim.x >> 4) + (threadIdx.x >> 4);
    if (node >= NN) return;
    int g = threadIdx.x & 15;
    int beg = __ldg(&rs[node]);
    int end = __ldg(&rs[node + 1]);

    const uint4* Y8 = (const uint4*)Yh;

    float f[8];
    {
        uint4 v = Y8[(size_t)node * 16 + g];  // self loop
        float2 a = __half22float2(*(__half2*)&v.x);
        float2 b = __half22float2(*(__half2*)&v.y);
        float2 c = __half22float2(*(__half2*)&v.z);
        float2 d = __half22float2(*(__half2*)&v.w);
        f[0] = a.x; f[1] = a.y; f[2] = b.x; f[3] = b.y;
        f[4] = c.x; f[5] = c.y; f[6] = d.x; f[7] = d.y;
    }

    int j = beg;
    for (; j + 8 <= end; j += 8) {
        int s0 = __ldg(&csr[j]);
        int s1 = __ldg(&csr[j + 1]);
        int s2 = __ldg(&csr[j + 2]);
        int s3 = __ldg(&csr[j + 3]);
        int s4 = __ldg(&csr[j + 4]);
        int s5 = __ldg(&csr[j + 5]);
        int s6 = __ldg(&csr[j + 6]);
        int s7 = __ldg(&csr[j + 7]);
        uint4 v0 = Y8[(size_t)s0 * 16 + g];
        uint4 v1 = Y8[(size_t)s1 * 16 + g];
        uint4 v2 = Y8[(size_t)s2 * 16 + g];
        uint4 v3 = Y8[(size_t)s3 * 16 + g];
        uint4 v4 = Y8[(size_t)s4 * 16 + g];
        uint4 v5 = Y8[(size_t)s5 * 16 + g];
        uint4 v6 = Y8[(size_t)s6 * 16 + g];
        uint4 v7 = Y8[(size_t)s7 * 16 + g];
        acc8(f, v0); acc8(f, v1); acc8(f, v2); acc8(f, v3);
        acc8(f, v4); acc8(f, v5); acc8(f, v6); acc8(f, v7);
    }
    if (j + 4 <= end) {
        int s0 = __ldg(&csr[j]);
        int s1 = __ldg(&csr[j + 1]);
        int s2 = __ldg(&csr[j + 2]);
        int s3 = __ldg(&csr[j + 3]);
        uint4 v0 = Y8[(size_t)s0 * 16 + g];
        uint4 v1 = Y8[(size_t)s1 * 16 + g];
        uint4 v2 = Y8[(size_t)s2 * 16 + g];
        uint4 v3 = Y8[(size_t)s3 * 16 + g];
        acc8(f, v0); acc8(f, v1); acc8(f, v2); acc8(f, v3);
        j += 4;
    }
    for (; j < end; j++) {
        int s = __ldg(&csr[j]);
        acc8(f, Y8[(size_t)s * 16 + g]);
    }

    float d = __ldg(&dinv[node]);
    float4 b0 = ((const float4*)bias)[g * 2];
    float4 b1 = ((const float4*)bias)[g * 2 + 1];
    float o[8];
    o[0] = b0.x + d * f[0]; o[1] = b0.y + d * f[1];
    o[2] = b0.z + d * f[2]; o[3] = b0.w + d * f[3];
    o[4] = b1.x + d * f[4]; o[5] = b1.y + d * f[5];
    o[6] = b1.z + d * f[6]; o[7] = b1.w + d * f[7];

    __half2 h0 = __float22half2_rn(make_float2(o[0], o[1]));
    __half2 h1 = __float22half2_rn(make_float2(o[2], o[3]));
    __half2 h2 = __float22half2_rn(make_float2(o[4], o[5]));
    __half2 h3 = __float22half2_rn(make_float2(o[6], o[7]));
    uint4 pkt;
    pkt.x = *(unsigned*)&h0; pkt.y = *(unsigned*)&h1;
    pkt.z = *(unsigned*)&h2; pkt.w = *(unsigned*)&h3;
    ((uint4*)Ah)[(size_t)node * 16 + g] = pkt;

    if (WRITE_LATENT) {
        float4* L = (float4*)&latent[(size_t)node * 128 + g * 8];
        L[0] = make_float4(fmaxf(o[0], 0.f), fmaxf(o[1], 0.f),
                           fmaxf(o[2], 0.f), fmaxf(o[3], 0.f));
        L[1] = make_float4(fmaxf(o[4], 0.f), fmaxf(o[5], 0.f),
                           fmaxf(o[6], 0.f), fmaxf(o[7], 0.f));
    }
}

// ---------------------------------------------------------------------------
// Aggregation gather (F=40): warp per node, lanes 0..19 half2 -> fp32 out.
// ---------------------------------------------------------------------------
__global__ void k_agg40(const int* __restrict__ rs, const int* __restrict__ csr,
                        const __half* __restrict__ Yh, const float* __restrict__ dinv,
                        const float* __restrict__ bias, float* __restrict__ A) {
    int node = blockIdx.x * (blockDim.x >> 5) + (threadIdx.x >> 5);
    if (node >= NN) return;
    int lane = threadIdx.x & 31;
    int beg = __ldg(&rs[node]);
    int end = __ldg(&rs[node + 1]);
    bool act = lane < 20;

    const unsigned* Y2 = (const unsigned*)Yh;
    float2 acc = make_float2(0.f, 0.f);
    if (act) {
        unsigned u = Y2[(size_t)node * 20 + lane];
        acc = __half22float2(*(__half2*)&u);
    }

    int j = beg;
    for (; j + 2 <= end; j += 2) {
        int s0 = __ldg(&csr[j]);
        int s1 = __ldg(&csr[j + 1]);
        if (act) {
            unsigned u0 = Y2[(size_t)s0 * 20 + lane];
            unsigned u1 = Y2[(size_t)s1 * 20 + lane];
            float2 v0 = __half22float2(*(__half2*)&u0);
            float2 v1 = __half22float2(*(__half2*)&u1);
            acc.x += v0.x + v1.x;
            acc.y += v0.y + v1.y;
        }
    }
    for (; j < end; j++) {
        int s = __ldg(&csr[j]);
        if (act) {
            unsigned u = Y2[(size_t)s * 20 + lane];
            float2 v = __half22float2(*(__half2*)&u);
            acc.x += v.x; acc.y += v.y;
        }
    }
    if (act) {
        float d = __ldg(&dinv[node]);
        float2 b = ((const float2*)bias)[lane];
        ((float2*)A)[(size_t)node * 20 + lane] =
            make_float2(b.x + d * acc.x, b.y + d * acc.y);
    }
}

// ---------------------------------------------------------------------------
// Launch
// ---------------------------------------------------------------------------
extern "C" void kernel_launch(void* const* d_in, const int* in_sizes, int n_in,
                              void* d_out, int out_size) {
    const float* x  = (const float*)d_in[0];
    const int*   ei = (const int*)d_in[1];
    const float* W1 = (const float*)d_in[2];
    const float* b1 = (const float*)d_in[3];
    const float* W2 = (const float*)d_in[4];
    const float* b2 = (const float*)d_in[5];
    const float* W3 = (const float*)d_in[6];
    const float* b3 = (const float*)d_in[7];
    const float* W4 = (const float*)d_in[8];
    const float* b4 = (const float*)d_in[9];

    float* out    = (float*)d_out;            // [NN, 40]
    float* latent = out + (size_t)NN * NC;    // [NN, 128]

    void *pdinv, *pth, *pah, *pwh, *pw4, *pcnt, *prs, *pcur, *pcsr, *pbs, *pbo;
    cudaGetSymbolAddress(&pdinv, g_dinv);
    cudaGetSymbolAddress(&pth,   g_th);
    cudaGetSymbolAddress(&pah,   g_ah);
    cudaGetSymbolAddress(&pwh,   g_wh);
    cudaGetSymbolAddress(&pw4,   g_w4h);
    cudaGetSymbolAddress(&pcnt,  g_cnt);
    cudaGetSymbolAddress(&prs,   g_rs);
    cudaGetSymbolAddress(&pcur,  g_cursor);
    cudaGetSymbolAddress(&pcsr,  g_csr);
    cudaGetSymbolAddress(&pbs,   g_bsum);
    cudaGetSymbolAddress(&pbo,   g_boff);
    float* dinv = (float*)pdinv;
    __half* th  = (__half*)pth;
    __half* ah  = (__half*)pah;
    __half* wh  = (__half*)pwh;
    __half* w4h = (__half*)pw4;
    int* cnt    = (int*)pcnt;
    int* rs     = (int*)prs;
    int* cursor = (int*)pcur;
    int* csr    = (int*)pcsr;
    int* bsum   = (int*)pbs;
    int* boff   = (int*)pbo;

    const int B = 256;
    const int MMA_SMEM   = (128 * PADH + 128 * PADH) * 2;  // 69632 B
    const int MMA40_SMEM = (64 * PADH + 128 * PAD40) * 2;  // 35840 B

    cudaFuncSetAttribute(k_gemm128_mma<float, false>,
                         cudaFuncAttributeMaxDynamicSharedMemorySize, MMA_SMEM);
    cudaFuncSetAttribute(k_gemm128_mma<__half, true>,
                         cudaFuncAttributeMaxDynamicSharedMemorySize, MMA_SMEM);
    cudaFuncSetAttribute(k_gemm40_mma,
                         cudaFuncAttributeMaxDynamicSharedMemorySize, MMA40_SMEM);

    // --- CSR build + normalization + weight conversion ---
    k_zero<<<(NN + B - 1) / B, B>>>(cnt);
    k_count<<<(NE + B - 1) / B, B>>>(ei, cnt);
    k_scan1<<<NB_SCAN, 1024>>>(cnt, rs, bsum);
    k_scan2<<<1, 128>>>(bsum, boff);
    k_scan3<<<(NN + B - 1) / B, B>>>(rs, cursor, boff, cnt, dinv);
    k_fill<<<(NE + B - 1) / B, B>>>(ei, cursor, csr);
    k_convW<<<64, 256>>>(W1, wh, 16384);
    k_convW<<<64, 256>>>(W2, wh + 16384, 16384);
    k_convW<<<64, 256>>>(W3, wh + 32768, 16384);
    k_convW4<<<32, 256>>>(W4, w4h);

    const int gemm_grid   = (NN + 127) / 128;
    const int gemm40_grid = (NN + 63) / 64;
    const int agg_grid    = (NN + 15) / 16;
    const int agg40_grid  = (NN + 7) / 8;

    // Layer 1
    k_gemm128_mma<float, false><<<gemm_grid, 512, MMA_SMEM>>>(x, wh, dinv, th, NN);
    k_agg128<false><<<agg_grid, 256>>>(rs, csr, th, dinv, b1, ah, nullptr);
    // Layer 2
    k_gemm128_mma<__half, true><<<gemm_grid, 512, MMA_SMEM>>>(ah, wh + 16384, dinv, th, NN);
    k_agg128<false><<<agg_grid, 256>>>(rs, csr, th, dinv, b2, ah, nullptr);
    // Layer 3 (+ latent)
    k_gemm128_mma<__half, true><<<gemm_grid, 512, MMA_SMEM>>>(ah, wh + 32768, dinv, th, NN);
    k_agg128<true><<<agg_grid, 256>>>(rs, csr, th, dinv, b3, ah, latent);
    // Layer 4
    k_gemm40_mma<<<gemm40_grid, 256, MMA40_SMEM>>>(ah, w4h, dinv, th, NN);
    k_agg40<<<agg40_grid, 256>>>(rs, csr, th, dinv, b4, out);
}

// round 16
// speedup vs baseline: 1.4626x; 1.4626x over previous
#include <cuda_runtime.h>
#include <cuda_bf16.h>
#include <cuda_fp16.h>
#include <cstdint>

#define NN 100000
#define NE 1600000
#define NF 128
#define NC 40
#define NB_SCAN ((NN + 1023) / 1024)
#define PADH 136   // halves per smem row (A/B 128-wide): 272 B stride, conflict-free
#define PAD40 72   // halves per smem row for 64-wide B tile: 144 B stride

// Scratch (device globals)
__device__ __align__(16) float g_dinv[NN];
__device__ __align__(16) __half g_th[(size_t)NN * NF];   // Y messages (fp16)
__device__ __align__(16) __half g_ah[(size_t)NN * NF];   // activations (fp16)
__device__ __align__(16) __half g_wh[3 * 128 * 128];     // fp16 weights (layers 1-3)
__device__ __align__(16) __half g_w4h[128 * 64];         // fp16 W4 padded to 64 cols
__device__ int g_cnt[NN];
__device__ int g_rs[NN + 1];
__device__ int g_cursor[NN];
__device__ int g_csr[NE];
__device__ int g_bsum[NB_SCAN];
__device__ int g_boff[NB_SCAN];

// ---------------------------------------------------------------------------
// Helpers
// ---------------------------------------------------------------------------
__device__ __forceinline__ void acc8(float* f, uint4 v) {
    float2 a = __half22float2(*(__half2*)&v.x);
    float2 b = __half22float2(*(__half2*)&v.y);
    float2 c = __half22float2(*(__half2*)&v.z);
    float2 d = __half22float2(*(__half2*)&v.w);
    f[0] += a.x; f[1] += a.y; f[2] += b.x; f[3] += b.y;
    f[4] += c.x; f[5] += c.y; f[6] += d.x; f[7] += d.y;
}

__device__ __forceinline__ uint4 relu_h8(uint4 v) {
    __half2 z = __float2half2_rn(0.f);
    __half2* h = (__half2*)&v;
    h[0] = __hmax2(h[0], z); h[1] = __hmax2(h[1], z);
    h[2] = __hmax2(h[2], z); h[3] = __hmax2(h[3], z);
    return v;
}

// ---------------------------------------------------------------------------
// CSR build
// ---------------------------------------------------------------------------
__global__ void k_zero(int* cnt) {
    int i = blockIdx.x * blockDim.x + threadIdx.x;
    if (i < NN) cnt[i] = 0;
}

__global__ void k_count(const int* __restrict__ ei, int* cnt) {
    int e = blockIdx.x * blockDim.x + threadIdx.x;
    if (e < NE) atomicAdd(&cnt[ei[NE + e]], 1);
}

__global__ void k_dinv(const int* __restrict__ cnt, float* dinv) {
    int i = blockIdx.x * blockDim.x + threadIdx.x;
    if (i < NN) dinv[i] = rsqrtf((float)(cnt[i] + 1));
}

__global__ void k_scan1(const int* __restrict__ cnt, int* rs, int* bsum) {
    __shared__ int s[1024];
    int i = blockIdx.x * 1024 + threadIdx.x;
    int v = (i < NN) ? cnt[i] : 0;
    s[threadIdx.x] = v;
    __syncthreads();
#pragma unroll
    for (int o = 1; o < 1024; o <<= 1) {
        int t = (threadIdx.x >= o) ? s[threadIdx.x - o] : 0;
        __syncthreads();
        s[threadIdx.x] += t;
        __syncthreads();
    }
    if (i < NN) rs[i] = s[threadIdx.x] - v;
    if (threadIdx.x == 1023) bsum[blockIdx.x] = s[1023];
}

__global__ void k_scan2(const int* __restrict__ bsum, int* boff) {
    __shared__ int s[NB_SCAN];
    if (threadIdx.x < NB_SCAN) s[threadIdx.x] = bsum[threadIdx.x];
    __syncthreads();
    if (threadIdx.x == 0) {
        int run = 0;
        for (int i = 0; i < NB_SCAN; i++) { int v = s[i]; s[i] = run; run += v; }
    }
    __syncthreads();
    if (threadIdx.x < NB_SCAN) boff[threadIdx.x] = s[threadIdx.x];
}

__global__ void k_scan3(int* rs, int* cursor, const int* __restrict__ boff) {
    int i = blockIdx.x * blockDim.x + threadIdx.x;
    if (i < NN) {
        int v = rs[i] + boff[i >> 10];
        rs[i] = v;
        cursor[i] = v;
    }
    if (i == 0) rs[NN] = NE;
}

__global__ void k_fill(const int* __restrict__ ei, int* cursor, int* csr) {
    int e = blockIdx.x * blockDim.x + threadIdx.x;
    if (e >= NE) return;
    int src = ei[e];
    int dst = ei[NE + e];
    int pos = atomicAdd(&cursor[dst], 1);
    csr[pos] = src;
}

__global__ void k_convW(const float* __restrict__ W, __half* __restrict__ Wh, int n) {
    int i = blockIdx.x * blockDim.x + threadIdx.x;
    if (i < n) Wh[i] = __float2half(W[i]);
}

__global__ void k_convW4(const float* __restrict__ W, __half* __restrict__ Wh) {
    int i = blockIdx.x * blockDim.x + threadIdx.x;
    if (i < 128 * 64) {
        int k = i >> 6, c = i & 63;
        Wh[i] = (c < 40) ? __float2half(W[k * 40 + c]) : __float2half(0.f);
    }
}

// ---------------------------------------------------------------------------
// Tensor-core GEMM: Yh[M,128] = half( dinv * (relu?(X) @ W) )
// BM=128, 512 threads, 16 warps = 8(M) x 2(N), warp tile m16 x n64.
// ---------------------------------------------------------------------------
template <typename TIN, bool RELU>
__global__ void __launch_bounds__(512)
k_gemm128_mma(const TIN* __restrict__ X, const __half* __restrict__ Wh,
              const float* __restrict__ dinv, __half* __restrict__ Yh, int M) {
    extern __shared__ __half sh[];
    __half* As = sh;                  // 128 x PADH
    __half* Bs = sh + 128 * PADH;     // 128 x PADH

    const int t    = threadIdx.x;
    const int warp = t >> 5;
    const int lane = t & 31;
    const int m0   = blockIdx.x * 128;
    const int wm   = (warp >> 1) * 16;
    const int wn   = (warp & 1) * 64;

    // Load A tile (128 rows x 128)
    if constexpr (sizeof(TIN) == 4) {
#pragma unroll
        for (int i = 0; i < 8; i++) {
            int idx = t + i * 512;
            int row = idx >> 5;
            int c4  = (idx & 31) * 4;
            float4 v = make_float4(0.f, 0.f, 0.f, 0.f);
            if (m0 + row < M)
                v = *(const float4*)&X[(size_t)(m0 + row) * 128 + c4];
            if (RELU) {
                v.x = fmaxf(v.x, 0.f); v.y = fmaxf(v.y, 0.f);
                v.z = fmaxf(v.z, 0.f); v.w = fmaxf(v.w, 0.f);
            }
            __half2 h0 = __float22half2_rn(make_float2(v.x, v.y));
            __half2 h1 = __float22half2_rn(make_float2(v.z, v.w));
            uint2 pkt;
            pkt.x = *(unsigned*)&h0;
            pkt.y = *(unsigned*)&h1;
            *(uint2*)&As[row * PADH + c4] = pkt;
        }
    } else {
#pragma unroll
        for (int i = 0; i < 4; i++) {
            int idx = t + i * 512;
            int row = idx >> 4;
            int c8  = (idx & 15) * 8;
            uint4 v = make_uint4(0, 0, 0, 0);
            if (m0 + row < M)
                v = *(const uint4*)&X[(size_t)(m0 + row) * 128 + c8];
            if (RELU) v = relu_h8(v);
            *(uint4*)&As[row * PADH + c8] = v;
        }
    }
    // Load B tile: 128 x 128 fp16
#pragma unroll
    for (int i = 0; i < 4; i++) {
        int idx = t + i * 512;
        int row = idx >> 4;
        int c8  = (idx & 15) * 8;
        *(uint4*)&Bs[row * PADH + c8] = *(const uint4*)&Wh[row * 128 + c8];
    }
    __syncthreads();

    float acc[8][4] = {};

    unsigned a_base = (unsigned)__cvta_generic_to_shared(As);
    unsigned b_base = (unsigned)__cvta_generic_to_shared(Bs);
    int lrow = lane & 15;
    int lcol = (lane >> 4) * 8;

#pragma unroll
    for (int k0 = 0; k0 < 128; k0 += 16) {
        unsigned a_addr = a_base + ((wm + lrow) * PADH + k0 + lcol) * 2;
        unsigned r0, r1, r2, r3;
        asm volatile("ldmatrix.sync.aligned.m8n8.x4.shared.b16 {%0,%1,%2,%3}, [%4];"
                     : "=r"(r0), "=r"(r1), "=r"(r2), "=r"(r3) : "r"(a_addr));
#pragma unroll
        for (int j = 0; j < 4; j++) {
            unsigned b_addr = b_base + ((k0 + lrow) * PADH + wn + j * 16 + lcol) * 2;
            unsigned b0, b1, b2, b3;
            asm volatile("ldmatrix.sync.aligned.m8n8.x4.trans.shared.b16 {%0,%1,%2,%3}, [%4];"
                         : "=r"(b0), "=r"(b1), "=r"(b2), "=r"(b3) : "r"(b_addr));
            asm volatile("mma.sync.aligned.m16n8k16.row.col.f32.f16.f16.f32 "
                         "{%0,%1,%2,%3}, {%4,%5,%6,%7}, {%8,%9}, {%0,%1,%2,%3};"
                         : "+f"(acc[2*j][0]), "+f"(acc[2*j][1]),
                           "+f"(acc[2*j][2]), "+f"(acc[2*j][3])
                         : "r"(r0), "r"(r1), "r"(r2), "r"(r3), "r"(b0), "r"(b1));
            asm volatile("mma.sync.aligned.m16n8k16.row.col.f32.f16.f16.f32 "
                         "{%0,%1,%2,%3}, {%4,%5,%6,%7}, {%8,%9}, {%0,%1,%2,%3};"
                         : "+f"(acc[2*j+1][0]), "+f"(acc[2*j+1][1]),
                           "+f"(acc[2*j+1][2]), "+f"(acc[2*j+1][3])
                         : "r"(r0), "r"(r1), "r"(r2), "r"(r3), "r"(b2), "r"(b3));
        }
    }

    int rq = lane >> 2;
    int cq = 2 * (lane & 3);
    int row0 = m0 + wm + rq;
    int row1 = row0 + 8;
    float d0 = (row0 < M) ? __ldg(&dinv[row0]) : 0.f;
    float d1 = (row1 < M) ? __ldg(&dinv[row1]) : 0.f;
#pragma unroll
    for (int j = 0; j < 8; j++) {
        int col = wn + j * 8 + cq;
        if (row0 < M) {
            __half2 h = __float22half2_rn(make_float2(d0 * acc[j][0], d0 * acc[j][1]));
            *(unsigned*)&Yh[(size_t)row0 * 128 + col] = *(unsigned*)&h;
        }
        if (row1 < M) {
            __half2 h = __float22half2_rn(make_float2(d1 * acc[j][2], d1 * acc[j][3]));
            *(unsigned*)&Yh[(size_t)row1 * 128 + col] = *(unsigned*)&h;
        }
    }
}

// ---------------------------------------------------------------------------
// Tensor-core GEMM (layer 4): Yh[M,40] = half( dinv * (relu(Ah) @ W4pad) )
// BM=64, 256 threads, 8 warps = 4(M) x 2(N), warp tile m16 x n32 (N padded 64).
// ---------------------------------------------------------------------------
__global__ void __launch_bounds__(256)
k_gemm40_mma(const __half* __restrict__ Ah, const __half* __restrict__ W4h,
             const float* __restrict__ dinv, __half* __restrict__ Yh, int M) {
    extern __shared__ __half sh[];
    __half* As = sh;                  // 64 x PADH
    __half* Bs = sh + 64 * PADH;      // 128 x PAD40

    const int t    = threadIdx.x;
    const int warp = t >> 5;
    const int lane = t & 31;
    const int m0   = blockIdx.x * 64;
    const int wm   = (warp >> 1) * 16;
    const int wn   = (warp & 1) * 32;

#pragma unroll
    for (int i = 0; i < 4; i++) {
        int idx = t + i * 256;
        int row = idx >> 4;
        int c8  = (idx & 15) * 8;
        uint4 v = make_uint4(0, 0, 0, 0);
        if (m0 + row < M)
            v = *(const uint4*)&Ah[(size_t)(m0 + row) * 128 + c8];
        v = relu_h8(v);
        *(uint4*)&As[row * PADH + c8] = v;
    }
#pragma unroll
    for (int i = 0; i < 4; i++) {
        int idx = t + i * 256;
        int row = idx >> 3;
        int c8  = (idx & 7) * 8;
        *(uint4*)&Bs[row * PAD40 + c8] = *(const uint4*)&W4h[row * 64 + c8];
    }
    __syncthreads();

    float acc[4][4] = {};

    unsigned a_base = (unsigned)__cvta_generic_to_shared(As);
    unsigned b_base = (unsigned)__cvta_generic_to_shared(Bs);
    int lrow = lane & 15;
    int lcol = (lane >> 4) * 8;

#pragma unroll
    for (int k0 = 0; k0 < 128; k0 += 16) {
        unsigned a_addr = a_base + ((wm + lrow) * PADH + k0 + lcol) * 2;
        unsigned r0, r1, r2, r3;
        asm volatile("ldmatrix.sync.aligned.m8n8.x4.shared.b16 {%0,%1,%2,%3}, [%4];"
                     : "=r"(r0), "=r"(r1), "=r"(r2), "=r"(r3) : "r"(a_addr));
#pragma unroll
        for (int j = 0; j < 2; j++) {
            unsigned b_addr = b_base + ((k0 + lrow) * PAD40 + wn + j * 16 + lcol) * 2;
            unsigned b0, b1, b2, b3;
            asm volatile("ldmatrix.sync.aligned.m8n8.x4.trans.shared.b16 {%0,%1,%2,%3}, [%4];"
                         : "=r"(b0), "=r"(b1), "=r"(b2), "=r"(b3) : "r"(b_addr));
            asm volatile("mma.sync.aligned.m16n8k16.row.col.f32.f16.f16.f32 "
                         "{%0,%1,%2,%3}, {%4,%5,%6,%7}, {%8,%9}, {%0,%1,%2,%3};"
                         : "+f"(acc[2*j][0]), "+f"(acc[2*j][1]),
                           "+f"(acc[2*j][2]), "+f"(acc[2*j][3])
                         : "r"(r0), "r"(r1), "r"(r2), "r"(r3), "r"(b0), "r"(b1));
            asm volatile("mma.sync.aligned.m16n8k16.row.col.f32.f16.f16.f32 "
                         "{%0,%1,%2,%3}, {%4,%5,%6,%7}, {%8,%9}, {%0,%1,%2,%3};"
                         : "+f"(acc[2*j+1][0]), "+f"(acc[2*j+1][1]),
                           "+f"(acc[2*j+1][2]), "+f"(acc[2*j+1][3])
                         : "r"(r0), "r"(r1), "r"(r2), "r"(r3), "r"(b2), "r"(b3));
        }
    }

    int rq = lane >> 2;
    int cq = 2 * (lane & 3);
    int row0 = m0 + wm + rq;
    int row1 = row0 + 8;
    float d0 = (row0 < M) ? __ldg(&dinv[row0]) : 0.f;
    float d1 = (row1 < M) ? __ldg(&dinv[row1]) : 0.f;
#pragma unroll
    for (int j = 0; j < 4; j++) {
        int col = wn + j * 8 + cq;
        if (col < 40) {
            if (row0 < M) {
                __half2 h = __float22half2_rn(make_float2(d0 * acc[j][0], d0 * acc[j][1]));
                *(unsigned*)&Yh[(size_t)row0 * 40 + col] = *(unsigned*)&h;
            }
            if (row1 < M) {
                __half2 h = __float22half2_rn(make_float2(d1 * acc[j][2], d1 * acc[j][3]));
                *(unsigned*)&Yh[(size_t)row1 * 40 + col] = *(unsigned*)&h;
            }
        }
    }
}

// ---------------------------------------------------------------------------
// Aggregation gather (F=128): 16-lane group per node, uint4 loads.
// ---------------------------------------------------------------------------
template <bool WRITE_LATENT>
__global__ void k_agg128(const int* __restrict__ rs, const int* __restrict__ csr,
                         const __half* __restrict__ Yh, const float* __restrict__ dinv,
                         const float* __restrict__ bias, __half* __restrict__ Ah,
                         float* __restrict__ latent) {
    int node = blockIdx.x * (blockDim.x >> 4) + (threadIdx.x >> 4);
    if (node >= NN) return;
    int g = threadIdx.x & 15;
    int beg = __ldg(&rs[node]);
    int end = __ldg(&rs[node + 1]);

    const uint4* Y8 = (const uint4*)Yh;

    float f[8];
    {
        uint4 v = Y8[(size_t)node * 16 + g];
        float2 a = __half22float2(*(__half2*)&v.x);
        float2 b = __half22float2(*(__half2*)&v.y);
        float2 c = __half22float2(*(__half2*)&v.z);
        float2 d = __half22float2(*(__half2*)&v.w);
        f[0] = a.x; f[1] = a.y; f[2] = b.x; f[3] = b.y;
        f[4] = c.x; f[5] = c.y; f[6] = d.x; f[7] = d.y;
    }

    int j = beg;
    for (; j + 4 <= end; j += 4) {
        int s0 = __ldg(&csr[j]);
        int s1 = __ldg(&csr[j + 1]);
        int s2 = __ldg(&csr[j + 2]);
        int s3 = __ldg(&csr[j + 3]);
        uint4 v0 = Y8[(size_t)s0 * 16 + g];
        uint4 v1 = Y8[(size_t)s1 * 16 + g];
        uint4 v2 = Y8[(size_t)s2 * 16 + g];
        uint4 v3 = Y8[(size_t)s3 * 16 + g];
        acc8(f, v0); acc8(f, v1); acc8(f, v2); acc8(f, v3);
    }
    for (; j < end; j++) {
        int s = __ldg(&csr[j]);
        acc8(f, Y8[(size_t)s * 16 + g]);
    }

    float d = __ldg(&dinv[node]);
    float4 b0 = ((const float4*)bias)[g * 2];
    float4 b1 = ((const float4*)bias)[g * 2 + 1];
    float o[8];
    o[0] = b0.x + d * f[0]; o[1] = b0.y + d * f[1];
    o[2] = b0.z + d * f[2]; o[3] = b0.w + d * f[3];
    o[4] = b1.x + d * f[4]; o[5] = b1.y + d * f[5];
    o[6] = b1.z + d * f[6]; o[7] = b1.w + d * f[7];

    __half2 h0 = __float22half2_rn(make_float2(o[0], o[1]));
    __half2 h1 = __float22half2_rn(make_float2(o[2], o[3]));
    __half2 h2 = __float22half2_rn(make_float2(o[4], o[5]));
    __half2 h3 = __float22half2_rn(make_float2(o[6], o[7]));
    uint4 pkt;
    pkt.x = *(unsigned*)&h0; pkt.y = *(unsigned*)&h1;
    pkt.z = *(unsigned*)&h2; pkt.w = *(unsigned*)&h3;
    ((uint4*)Ah)[(size_t)node * 16 + g] = pkt;

    if (WRITE_LATENT) {
        float4* L = (float4*)&latent[(size_t)node * 128 + g * 8];
        L[0] = make_float4(fmaxf(o[0], 0.f), fmaxf(o[1], 0.f),
                           fmaxf(o[2], 0.f), fmaxf(o[3], 0.f));
        L[1] = make_float4(fmaxf(o[4], 0.f), fmaxf(o[5], 0.f),
                           fmaxf(o[6], 0.f), fmaxf(o[7], 0.f));
    }
}

// ---------------------------------------------------------------------------
// Aggregation gather (F=40): warp per node, lanes 0..19 half2 -> fp32 out.
// ---------------------------------------------------------------------------
__global__ void k_agg40(const int* __restrict__ rs, const int* __restrict__ csr,
                        const __half* __restrict__ Yh, const float* __restrict__ dinv,
                        const float* __restrict__ bias, float* __restrict__ A) {
    int node = blockIdx.x * (blockDim.x >> 5) + (threadIdx.x >> 5);
    if (node >= NN) return;
    int lane = threadIdx.x & 31;
    int beg = __ldg(&rs[node]);
    int end = __ldg(&rs[node + 1]);
    bool act = lane < 20;

    const unsigned* Y2 = (const unsigned*)Yh;
    float2 acc = make_float2(0.f, 0.f);
    if (act) {
        unsigned u = Y2[(size_t)node * 20 + lane];
        acc = __half22float2(*(__half2*)&u);
    }

    int j = beg;
    for (; j + 2 <= end; j += 2) {
        int s0 = __ldg(&csr[j]);
        int s1 = __ldg(&csr[j + 1]);
        if (act) {
            unsigned u0 = Y2[(size_t)s0 * 20 + lane];
            unsigned u1 = Y2[(size_t)s1 * 20 + lane];
            float2 v0 = __half22float2(*(__half2*)&u0);
            float2 v1 = __half22float2(*(__half2*)&u1);
            acc.x += v0.x + v1.x;
            acc.y += v0.y + v1.y;
        }
    }
    for (; j < end; j++) {
        int s = __ldg(&csr[j]);
        if (act) {
            unsigned u = Y2[(size_t)s * 20 + lane];
            float2 v = __half22float2(*(__half2*)&u);
            acc.x += v.x; acc.y += v.y;
        }
    }
    if (act) {
        float d = __ldg(&dinv[node]);
        float2 b = ((const float2*)bias)[lane];
        ((float2*)A)[(size_t)node * 20 + lane] =
            make_float2(b.x + d * acc.x, b.y + d * acc.y);
    }
}

// ---------------------------------------------------------------------------
// Launch
// ---------------------------------------------------------------------------
extern "C" void kernel_launch(void* const* d_in, const int* in_sizes, int n_in,
                              void* d_out, int out_size) {
    const float* x  = (const float*)d_in[0];
    const int*   ei = (const int*)d_in[1];
    const float* W1 = (const float*)d_in[2];
    const float* b1 = (const float*)d_in[3];
    const float* W2 = (const float*)d_in[4];
    const float* b2 = (const float*)d_in[5];
    const float* W3 = (const float*)d_in[6];
    const float* b3 = (const float*)d_in[7];
    const float* W4 = (const float*)d_in[8];
    const float* b4 = (const float*)d_in[9];

    float* out    = (float*)d_out;            // [NN, 40]
    float* latent = out + (size_t)NN * NC;    // [NN, 128]

    void *pdinv, *pth, *pah, *pwh, *pw4, *pcnt, *prs, *pcur, *pcsr, *pbs, *pbo;
    cudaGetSymbolAddress(&pdinv, g_dinv);
    cudaGetSymbolAddress(&pth,   g_th);
    cudaGetSymbolAddress(&pah,   g_ah);
    cudaGetSymbolAddress(&pwh,   g_wh);
    cudaGetSymbolAddress(&pw4,   g_w4h);
    cudaGetSymbolAddress(&pcnt,  g_cnt);
    cudaGetSymbolAddress(&prs,   g_rs);
    cudaGetSymbolAddress(&pcur,  g_cursor);
    cudaGetSymbolAddress(&pcsr,  g_csr);
    cudaGetSymbolAddress(&pbs,   g_bsum);
    cudaGetSymbolAddress(&pbo,   g_boff);
    float* dinv = (float*)pdinv;
    __half* th  = (__half*)pth;
    __half* ah  = (__half*)pah;
    __half* wh  = (__half*)pwh;
    __half* w4h = (__half*)pw4;
    int* cnt    = (int*)pcnt;
    int* rs     = (int*)prs;
    int* cursor = (int*)pcur;
    int* csr    = (int*)pcsr;
    int* bsum   = (int*)pbs;
    int* boff   = (int*)pbo;

    const int B = 256;
    const int MMA_SMEM   = (128 * PADH + 128 * PADH) * 2;  // 69632 B
    const int MMA40_SMEM = (64 * PADH + 128 * PAD40) * 2;  // 35840 B

    cudaFuncSetAttribute(k_gemm128_mma<float, false>,
                         cudaFuncAttributeMaxDynamicSharedMemorySize, MMA_SMEM);
    cudaFuncSetAttribute(k_gemm128_mma<__half, true>,
                         cudaFuncAttributeMaxDynamicSharedMemorySize, MMA_SMEM);
    cudaFuncSetAttribute(k_gemm40_mma,
                         cudaFuncAttributeMaxDynamicSharedMemorySize, MMA40_SMEM);

    // --- CSR build + normalization + weight conversion ---
    k_zero<<<(NN + B - 1) / B, B>>>(cnt);
    k_count<<<(NE + B - 1) / B, B>>>(ei, cnt);
    k_dinv<<<(NN + B - 1) / B, B>>>(cnt, dinv);
    k_scan1<<<NB_SCAN, 1024>>>(cnt, rs, bsum);
    k_scan2<<<1, 128>>>(bsum, boff);
    k_scan3<<<(NN + B - 1) / B, B>>>(rs, cursor, boff);
    k_fill<<<(NE + B - 1) / B, B>>>(ei, cursor, csr);
    k_convW<<<64, 256>>>(W1, wh, 16384);
    k_convW<<<64, 256>>>(W2, wh + 16384, 16384);
    k_convW<<<64, 256>>>(W3, wh + 32768, 16384);
    k_convW4<<<32, 256>>>(W4, w4h);

    const int gemm_grid   = (NN + 127) / 128;
    const int gemm40_grid = (NN + 63) / 64;
    const int agg_grid    = (NN + 15) / 16;
    const int agg40_grid  = (NN + 7) / 8;

    // Layer 1
    k_gemm128_mma<float, false><<<gemm_grid, 512, MMA_SMEM>>>(x, wh, dinv, th, NN);
    k_agg128<false><<<agg_grid, 256>>>(rs, csr, th, dinv, b1, ah, nullptr);
    // Layer 2
    k_gemm128_mma<__half, true><<<gemm_grid, 512, MMA_SMEM>>>(ah, wh + 16384, dinv, th, NN);
    k_agg128<false><<<agg_grid, 256>>>(rs, csr, th, dinv, b2, ah, nullptr);
    // Layer 3 (+ latent)
    k_gemm128_mma<__half, true><<<gemm_grid, 512, MMA_SMEM>>>(ah, wh + 32768, dinv, th, NN);
    k_agg128<true><<<agg_grid, 256>>>(rs, csr, th, dinv, b3, ah, latent);
    // Layer 4
    k_gemm40_mma<<<gemm40_grid, 256, MMA40_SMEM>>>(ah, w4h, dinv, th, NN);
    k_agg40<<<agg40_grid, 256>>>(rs, csr, th, dinv, b4, out);
}